// round 15
// baseline (speedup 1.0000x reference)
#include <cuda_runtime.h>

#define N_NODES 10000
#define N_EDGES 640000
#define D 128
#define CAP 160              // per-receiver bucket capacity (max degree ~100)
#define NPB 8                // nodes per fused block (8 warps, 256 threads)

// Scratch (allocation-free rule: __device__ globals).
// g_count starts zero (static init) and is re-zeroed by fused_kernel each run.
__device__ int g_count[N_NODES];          // in-degree (also placement cursor)
__device__ int g_ss[N_NODES * CAP];       // sender ids, bucketed by receiver

// ---------------------------------------------------------------------------
// K1: bucketed CSR build — ONE atomic yields both count and position.
// ---------------------------------------------------------------------------
__global__ void __launch_bounds__(256) place_kernel(
    const int* __restrict__ senders, const int* __restrict__ receivers) {
    int e = blockIdx.x * blockDim.x + threadIdx.x;
    if (e >= N_EDGES) return;
    int r = __ldg(receivers + e);
    int s = __ldg(senders + e);
    int pos = atomicAdd(&g_count[r], 1);
    if (pos < CAP) g_ss[(size_t)r * CAP + pos] = s;
}

// ---------------------------------------------------------------------------
// K2 (fused): gather/accumulate/normalize 8 nodes into smem, then project
// them through W with a split-k f32x2 GEMM, all in one block.
// g_count[node] is reset to 0 after the (single) read, replacing the zero
// kernel entirely.
// ---------------------------------------------------------------------------
__device__ __forceinline__ unsigned long long pack2(float lo, float hi) {
    unsigned long long r;
    asm("mov.b64 %0, {%1, %2};" : "=l"(r) : "f"(lo), "f"(hi));
    return r;
}

#define PS_IDX(idx, w, lane) (((idx) * 8 + (w)) * 33 + (lane))

__global__ void __launch_bounds__(256, 4) fused_kernel(
    const float* __restrict__ nodes,
    const float* __restrict__ W,
    const float* __restrict__ b,
    float* __restrict__ out)
{
    __shared__ float As[NPB][D];                       // 4 KB, A rows
    __shared__ unsigned long long Ps[64 * 33];         // 16.9 KB, k-partials

    int tid  = threadIdx.x;
    int w    = tid >> 5;
    int lane = tid & 31;

    // ---------------- Phase 1: gather + accumulate + normalize -------------
    {
        int node = blockIdx.x * NPB + w;
        int cnt_raw = g_count[node];
        if (lane == 0) g_count[node] = 0;   // reset for next replay (sole reader)
        int cnt = min(cnt_raw, CAP);
        const int* bucket = g_ss + (size_t)node * CAP;

        const float4* nodes4 = reinterpret_cast<const float4*>(nodes);
        float4 acc = make_float4(0.f, 0.f, 0.f, 0.f);

        int i = 0;
        for (; i + 8 <= cnt; i += 8) {
            int s[8];
            #pragma unroll
            for (int k = 0; k < 8; k++) s[k] = __ldg(bucket + i + k);
            float4 v[8];
            #pragma unroll
            for (int k = 0; k < 8; k++) v[k] = __ldg(nodes4 + (size_t)s[k] * 32 + lane);
            #pragma unroll
            for (int k = 0; k < 8; k++) {
                acc.x += v[k].x; acc.y += v[k].y; acc.z += v[k].z; acc.w += v[k].w;
            }
        }
        for (; i < cnt; i++) {
            int s = __ldg(bucket + i);
            float4 v = __ldg(nodes4 + (size_t)s * 32 + lane);
            acc.x += v.x; acc.y += v.y; acc.z += v.z; acc.w += v.w;
        }

        float invd = 1.0f / fmaxf((float)cnt_raw, 1.0f);
        acc.x *= invd; acc.y *= invd; acc.z *= invd; acc.w *= invd;
        reinterpret_cast<float4*>(&As[w][0])[lane] = acc;
    }
    __syncthreads();

    // ---------------- Phase 2: split-k f32x2 GEMM ---------------------------
    {
        int kq = w >> 1;          // k-quarter 0..3
        int ng = w & 1;           // node group 0..1 (nodes ng*4 .. ng*4+3)
        int n0 = ng * 4;
        int cg = lane;            // cols cg*4 .. cg*4+3

        unsigned long long acc2[8];
        #pragma unroll
        for (int i = 0; i < 8; i++) acc2[i] = 0ULL;

        const float4* W4 = reinterpret_cast<const float4*>(W);

        int kbeg = kq * 32;
        #pragma unroll 4
        for (int kk = 0; kk < 32; kk++) {
            int k = kbeg + kk;
            float a0 = As[n0 + 0][k];
            float a1 = As[n0 + 1][k];
            float a2 = As[n0 + 2][k];
            float a3 = As[n0 + 3][k];
            unsigned long long ap[2];
            ap[0] = pack2(a0, a1);
            ap[1] = pack2(a2, a3);

            float4 w4 = __ldg(W4 + k * (D / 4) + cg);
            unsigned long long w2[4];
            w2[0] = pack2(w4.x, w4.x);
            w2[1] = pack2(w4.y, w4.y);
            w2[2] = pack2(w4.z, w4.z);
            w2[3] = pack2(w4.w, w4.w);

            #pragma unroll
            for (int pp = 0; pp < 2; pp++)
                #pragma unroll
                for (int c = 0; c < 4; c++)
                    asm("fma.rn.f32x2 %0, %1, %2, %0;"
                        : "+l"(acc2[pp * 4 + c]) : "l"(ap[pp]), "l"(w2[c]));
        }

        #pragma unroll
        for (int idx = 0; idx < 8; idx++)
            Ps[PS_IDX(idx, w, lane)] = acc2[idx];
    }
    __syncthreads();

    // ---------------- Reduce k-partials + bias + store ----------------------
    {
        int ng = tid >> 7;            // 0..1
        int rem = tid & 127;
        int cg = rem >> 2;            // 0..31
        int c  = rem & 3;             // 0..3
        int j  = cg * 4 + c;          // output column

        float bj = __ldg(b + j);

        #pragma unroll
        for (int pp = 0; pp < 2; pp++) {
            int idx = pp * 4 + c;
            unsigned long long s = Ps[PS_IDX(idx, 0 * 2 + ng, cg)];
            #pragma unroll
            for (int kq = 1; kq < 4; kq++) {
                unsigned long long p = Ps[PS_IDX(idx, kq * 2 + ng, cg)];
                asm("add.rn.f32x2 %0, %0, %1;" : "+l"(s) : "l"(p));
            }
            float lo, hi;
            asm("mov.b64 {%0, %1}, %2;" : "=f"(lo), "=f"(hi) : "l"(s));

            int n_lo = blockIdx.x * NPB + ng * 4 + pp * 2;
            out[(size_t)n_lo * D + j]       = lo + bj;
            out[(size_t)(n_lo + 1) * D + j] = hi + bj;
        }
    }
}

// ---------------------------------------------------------------------------
// Launch
// ---------------------------------------------------------------------------
extern "C" void kernel_launch(void* const* d_in, const int* in_sizes, int n_in,
                              void* d_out, int out_size) {
    const float* nodes     = (const float*)d_in[0];
    const int*   senders   = (const int*)d_in[1];
    const int*   receivers = (const int*)d_in[2];
    const float* W         = (const float*)d_in[3];
    const float* b         = (const float*)d_in[4];
    float* out = (float*)d_out;

    place_kernel<<<(N_EDGES + 255) / 256, 256>>>(senders, receivers);
    fused_kernel<<<N_NODES / NPB, 256>>>(nodes, W, b, out);
}

// round 16
// speedup vs baseline: 1.0336x; 1.0336x over previous
#include <cuda_runtime.h>

#define N_NODES 10000
#define N_EDGES 640000
#define D 128
#define CAP 160              // per-receiver bucket capacity (max degree ~100)
#define NPB 8                // nodes per fused block (8 warps, 256 threads)

// Scratch (allocation-free rule: __device__ globals).
// g_count starts zero (static init) and is re-zeroed by fused_kernel each run.
__device__ int g_count[N_NODES];          // in-degree (also placement cursor)
__device__ int g_ss[N_NODES * CAP];       // sender ids, bucketed by receiver

// ---------------------------------------------------------------------------
// K1: bucketed CSR build — ONE atomic yields both count and position.
// ---------------------------------------------------------------------------
__global__ void __launch_bounds__(256) place_kernel(
    const int* __restrict__ senders, const int* __restrict__ receivers) {
    int e = blockIdx.x * blockDim.x + threadIdx.x;
    if (e >= N_EDGES) return;
    int r = __ldg(receivers + e);
    int s = __ldg(senders + e);
    int pos = atomicAdd(&g_count[r], 1);
    if (pos < CAP) g_ss[(size_t)r * CAP + pos] = s;
}

// ---------------------------------------------------------------------------
// K2 (fused): gather/accumulate/normalize 8 nodes into smem, then project
// them through W with a split-k f32x2 GEMM, all in one block.
// g_count[node] is reset to 0 after the (single) read, replacing the zero
// kernel entirely. NO min-blocks clause: R14 showed forcing 4 blocks/SM
// spills phase-1 state to local memory (+10us). Instead the gather unroll is
// reduced 8 -> 4 to shrink the natural register footprint (4 float4 + 4 ids
// in flight; 32 outstanding loads/block still covers L2 latency).
// ---------------------------------------------------------------------------
__device__ __forceinline__ unsigned long long pack2(float lo, float hi) {
    unsigned long long r;
    asm("mov.b64 %0, {%1, %2};" : "=l"(r) : "f"(lo), "f"(hi));
    return r;
}

#define PS_IDX(idx, w, lane) (((idx) * 8 + (w)) * 33 + (lane))

__global__ void __launch_bounds__(256) fused_kernel(
    const float* __restrict__ nodes,
    const float* __restrict__ W,
    const float* __restrict__ b,
    float* __restrict__ out)
{
    __shared__ float As[NPB][D];                       // 4 KB, A rows
    __shared__ unsigned long long Ps[64 * 33];         // 16.9 KB, k-partials

    int tid  = threadIdx.x;
    int w    = tid >> 5;
    int lane = tid & 31;

    // ---------------- Phase 1: gather + accumulate + normalize -------------
    {
        int node = blockIdx.x * NPB + w;
        int cnt_raw = g_count[node];
        if (lane == 0) g_count[node] = 0;   // reset for next replay (sole reader)
        int cnt = min(cnt_raw, CAP);
        const int* bucket = g_ss + (size_t)node * CAP;

        const float4* nodes4 = reinterpret_cast<const float4*>(nodes);
        float4 acc = make_float4(0.f, 0.f, 0.f, 0.f);

        int i = 0;
        for (; i + 4 <= cnt; i += 4) {
            int s0 = __ldg(bucket + i + 0);
            int s1 = __ldg(bucket + i + 1);
            int s2 = __ldg(bucket + i + 2);
            int s3 = __ldg(bucket + i + 3);
            float4 v0 = __ldg(nodes4 + (size_t)s0 * 32 + lane);
            float4 v1 = __ldg(nodes4 + (size_t)s1 * 32 + lane);
            float4 v2 = __ldg(nodes4 + (size_t)s2 * 32 + lane);
            float4 v3 = __ldg(nodes4 + (size_t)s3 * 32 + lane);
            acc.x += v0.x + v1.x + v2.x + v3.x;
            acc.y += v0.y + v1.y + v2.y + v3.y;
            acc.z += v0.z + v1.z + v2.z + v3.z;
            acc.w += v0.w + v1.w + v2.w + v3.w;
        }
        for (; i < cnt; i++) {
            int s = __ldg(bucket + i);
            float4 v = __ldg(nodes4 + (size_t)s * 32 + lane);
            acc.x += v.x; acc.y += v.y; acc.z += v.z; acc.w += v.w;
        }

        float invd = 1.0f / fmaxf((float)cnt_raw, 1.0f);
        acc.x *= invd; acc.y *= invd; acc.z *= invd; acc.w *= invd;
        reinterpret_cast<float4*>(&As[w][0])[lane] = acc;
    }
    __syncthreads();

    // ---------------- Phase 2: split-k f32x2 GEMM ---------------------------
    {
        int kq = w >> 1;          // k-quarter 0..3
        int ng = w & 1;           // node group 0..1 (nodes ng*4 .. ng*4+3)
        int n0 = ng * 4;
        int cg = lane;            // cols cg*4 .. cg*4+3

        unsigned long long acc2[8];
        #pragma unroll
        for (int i = 0; i < 8; i++) acc2[i] = 0ULL;

        const float4* W4 = reinterpret_cast<const float4*>(W);

        int kbeg = kq * 32;
        #pragma unroll 4
        for (int kk = 0; kk < 32; kk++) {
            int k = kbeg + kk;
            float a0 = As[n0 + 0][k];
            float a1 = As[n0 + 1][k];
            float a2 = As[n0 + 2][k];
            float a3 = As[n0 + 3][k];
            unsigned long long ap[2];
            ap[0] = pack2(a0, a1);
            ap[1] = pack2(a2, a3);

            float4 w4 = __ldg(W4 + k * (D / 4) + cg);
            unsigned long long w2[4];
            w2[0] = pack2(w4.x, w4.x);
            w2[1] = pack2(w4.y, w4.y);
            w2[2] = pack2(w4.z, w4.z);
            w2[3] = pack2(w4.w, w4.w);

            #pragma unroll
            for (int pp = 0; pp < 2; pp++)
                #pragma unroll
                for (int c = 0; c < 4; c++)
                    asm("fma.rn.f32x2 %0, %1, %2, %0;"
                        : "+l"(acc2[pp * 4 + c]) : "l"(ap[pp]), "l"(w2[c]));
        }

        #pragma unroll
        for (int idx = 0; idx < 8; idx++)
            Ps[PS_IDX(idx, w, lane)] = acc2[idx];
    }
    __syncthreads();

    // ---------------- Reduce k-partials + bias + store ----------------------
    {
        int ng = tid >> 7;            // 0..1
        int rem = tid & 127;
        int cg = rem >> 2;            // 0..31
        int c  = rem & 3;             // 0..3
        int j  = cg * 4 + c;          // output column

        float bj = __ldg(b + j);

        #pragma unroll
        for (int pp = 0; pp < 2; pp++) {
            int idx = pp * 4 + c;
            unsigned long long s = Ps[PS_IDX(idx, 0 * 2 + ng, cg)];
            #pragma unroll
            for (int kq = 1; kq < 4; kq++) {
                unsigned long long p = Ps[PS_IDX(idx, kq * 2 + ng, cg)];
                asm("add.rn.f32x2 %0, %0, %1;" : "+l"(s) : "l"(p));
            }
            float lo, hi;
            asm("mov.b64 {%0, %1}, %2;" : "=f"(lo), "=f"(hi) : "l"(s));

            int n_lo = blockIdx.x * NPB + ng * 4 + pp * 2;
            out[(size_t)n_lo * D + j]       = lo + bj;
            out[(size_t)(n_lo + 1) * D + j] = hi + bj;
        }
    }
}

// ---------------------------------------------------------------------------
// Launch
// ---------------------------------------------------------------------------
extern "C" void kernel_launch(void* const* d_in, const int* in_sizes, int n_in,
                              void* d_out, int out_size) {
    const float* nodes     = (const float*)d_in[0];
    const int*   senders   = (const int*)d_in[1];
    const int*   receivers = (const int*)d_in[2];
    const float* W         = (const float*)d_in[3];
    const float* b         = (const float*)d_in[4];
    float* out = (float*)d_out;

    place_kernel<<<(N_EDGES + 255) / 256, 256>>>(senders, receivers);
    fused_kernel<<<N_NODES / NPB, 256>>>(nodes, W, b, out);
}